// round 4
// baseline (speedup 1.0000x reference)
#include <cuda_runtime.h>
#include <cstdint>

#define NN 100000
#define EE 1600000
#define IN_DIM 128
#define OUT_DIM 64
#define TT 8
#define EPS_ 1e-7f
#define CSR_CAP (EE + 8 * NN)          // padded CSR capacity

typedef unsigned long long ull;

// ---------------- scratch (no allocations allowed) ----------------
__device__ int   g_cnt[NN];                            // real in-degree
__device__ int   g_off[NN];                            // padded CSR offsets (multiple of 8)
__device__ int   g_cur[NN];                            // fill cursors
__device__ int   g_csr[CSR_CAP];                       // src per slot; padding = NN (dummy)
__device__ float g_dinv[NN];                           // 1/sqrt(deg+1)
__device__ float g_hs[(size_t)(NN + 1) * OUT_DIM];     // dinv[n]*(x@W); row NN = zeros

// ---------------- helpers ----------------
__device__ __forceinline__ float warp_sum(float v) {
#pragma unroll
    for (int o = 16; o > 0; o >>= 1) v += __shfl_xor_sync(0xffffffffu, v, o);
    return v;
}
__device__ __forceinline__ ull packdup(float a) {
    ull p; asm("mov.b64 %0, {%1, %1};" : "=l"(p) : "f"(a)); return p;
}
__device__ __forceinline__ ull pack2(float a, float b) {
    ull p; asm("mov.b64 %0, {%1, %2};" : "=l"(p) : "f"(a), "f"(b)); return p;
}
__device__ __forceinline__ void pfma(ull& acc, ull x, ull w) {
    asm("fma.rn.f32x2 %0, %1, %2, %0;" : "+l"(acc) : "l"(x), "l"(w));
}

// ---------------- kernels ----------------

// zero counts, fill padded CSR with dummy index NN, zero dummy h row
__global__ void init_kernel() {
    int i = blockIdx.x * blockDim.x + threadIdx.x;
    if (i < CSR_CAP) g_csr[i] = NN;
    if (i < NN) g_cnt[i] = 0;
    if (i < OUT_DIM) g_hs[(size_t)NN * OUT_DIM + i] = 0.0f;
}

__global__ void hist_kernel(const int* __restrict__ dst) {
    int e = blockIdx.x * blockDim.x + threadIdx.x;
    if (e >= EE) return;
    atomicAdd(&g_cnt[dst[e]], 1);
}

// single-block scan over padded counts: offsets, cursors, dinv
__global__ void scan_kernel() {
    __shared__ int part[1024];
    int tid = threadIdx.x;
    const int CH = (NN + 1023) / 1024;   // 98
    int lo = tid * CH;
    int hi = lo + CH; if (hi > NN) hi = NN;
    int s = 0;
    for (int i = lo; i < hi; i++) s += (g_cnt[i] + 7) & ~7;
    part[tid] = s;
    __syncthreads();
#pragma unroll
    for (int o = 1; o < 1024; o <<= 1) {
        int v = (tid >= o) ? part[tid - o] : 0;
        __syncthreads();
        part[tid] += v;
        __syncthreads();
    }
    int run = (tid > 0) ? part[tid - 1] : 0;
    for (int i = lo; i < hi; i++) {
        int c = g_cnt[i];
        g_off[i] = run;
        g_cur[i] = run;
        g_dinv[i] = rsqrtf((float)(c + 1));
        run += (c + 7) & ~7;
    }
}

// h_s = dinv * (x @ W): 64 nodes/block, 8 per warp, packed f32x2, x staged in smem
__global__ void gemm_kernel(const float* __restrict__ x, const float* __restrict__ W) {
    extern __shared__ ull sm[];
    ull* Wps = sm;            // [128][32] packed W pairs (32 KB)
    ull* xs2 = sm + 4096;     // [64 nodes][128 k] {x,x} (64 KB)

    int tid = threadIdx.x;
    const float2* Wf2 = (const float2*)W;
    for (int i = tid; i < IN_DIM * OUT_DIM / 2; i += 256) {
        float2 w = Wf2[i];
        Wps[i] = pack2(w.x, w.y);
    }
    int n0 = blockIdx.x * 64;
    const float4* x4 = (const float4*)x;
    for (int idx = tid; idx < 64 * 32; idx += 256) {
        int node = idx >> 5, k4 = idx & 31;
        int gn = n0 + node;
        float4 v = (gn < NN) ? x4[(size_t)gn * 32 + k4]
                             : make_float4(0.f, 0.f, 0.f, 0.f);
        ull* dstp = xs2 + node * IN_DIM + 4 * k4;
        dstp[0] = packdup(v.x);
        dstp[1] = packdup(v.y);
        dstp[2] = packdup(v.z);
        dstp[3] = packdup(v.w);
    }
    __syncthreads();

    int wid = tid >> 5, lane = tid & 31;
    const ull* xw = xs2 + wid * 8 * IN_DIM;

    ull acc[8];
#pragma unroll
    for (int n = 0; n < 8; n++) acc[n] = 0ull;

#pragma unroll 4
    for (int k0 = 0; k0 < IN_DIM; k0 += 2) {
        ull w0 = Wps[k0 * 32 + lane];
        ull w1 = Wps[k0 * 32 + 32 + lane];
#pragma unroll
        for (int n = 0; n < 8; n++) {
            ulonglong2 xv = *(const ulonglong2*)(xw + n * IN_DIM + k0);
            pfma(acc[n], xv.x, w0);
            pfma(acc[n], xv.y, w1);
        }
    }

#pragma unroll
    for (int n = 0; n < 8; n++) {
        int gn = n0 + wid * 8 + n;
        if (gn >= NN) break;
        float2 v;
        asm("mov.b64 {%0, %1}, %2;" : "=f"(v.x), "=f"(v.y) : "l"(acc[n]));
        float di = g_dinv[gn];
        v.x *= di; v.y *= di;
        *(float2*)(g_hs + (size_t)gn * OUT_DIM + 2 * lane) = v;
    }
}

__global__ void bucket_kernel(const int* __restrict__ ei) {
    int e = blockIdx.x * blockDim.x + threadIdx.x;
    if (e >= EE) return;
    int s = ei[e];
    int d = ei[EE + e];
    int pos = atomicAdd(&g_cur[d], 1);
    g_csr[pos] = s;
}

// fused gather + 8-step Lorentz recurrence: one warp per node,
// lane holds components (2*lane, 2*lane+1); MLP-8 padded gather
__global__ void fused_kernel(const float* __restrict__ b,
                             float* __restrict__ o_out,
                             float* __restrict__ z_out) {
    int warp = (blockIdx.x * blockDim.x + threadIdx.x) >> 5;
    int lane = threadIdx.x & 31;
    if (warp >= NN) return;
    const int n = warp;
    const int c0 = 2 * lane;
    const size_t base = (size_t)n * OUT_DIM;

    int off = g_off[n];
    int mp = (g_cnt[n] + 7) & ~7;

    const float2* hs2 = (const float2*)g_hs;

    // self-loop contribution (hs already scaled by dinv[n])
    float2 acc = hs2[base / 2 + lane];

    for (int i = 0; i < mp; i += 8) {
        int4 a = __ldg((const int4*)(g_csr + off + i));
        int4 c = __ldg((const int4*)(g_csr + off + i + 4));
        float2 v0 = hs2[(size_t)a.x * 32 + lane];
        float2 v1 = hs2[(size_t)a.y * 32 + lane];
        float2 v2 = hs2[(size_t)a.z * 32 + lane];
        float2 v3 = hs2[(size_t)a.w * 32 + lane];
        float2 v4 = hs2[(size_t)c.x * 32 + lane];
        float2 v5 = hs2[(size_t)c.y * 32 + lane];
        float2 v6 = hs2[(size_t)c.z * 32 + lane];
        float2 v7 = hs2[(size_t)c.w * 32 + lane];
        acc.x += ((v0.x + v1.x) + (v2.x + v3.x)) + ((v4.x + v5.x) + (v6.x + v7.x));
        acc.y += ((v0.y + v1.y) + (v2.y + v3.y)) + ((v4.y + v5.y) + (v6.y + v7.y));
    }

    float di = g_dinv[n];
    float h0 = fmaf(di, acc.x, b[c0]);
    float h1 = fmaf(di, acc.y, b[c0 + 1]);

    float z0 = (lane == 0) ? 1.0f : 0.0f;   // time coordinate on lane 0
    float z1 = 0.0f;

#pragma unroll
    for (int t = 0; t < TT; t++) {
        float p = z0 * h0 + z1 * h1;
        float p00 = __shfl_sync(0xffffffffu, z0 * h0, 0);
        float lz = warp_sum(p) - 2.0f * p00;

        float u0 = fmaf(lz, z0, h0);
        float u1 = fmaf(lz, z1, h1);

        float q = u0 * u0 + u1 * u1;
        float q00 = __shfl_sync(0xffffffffu, u0 * u0, 0);
        float uu = warp_sum(q) - 2.0f * q00;
        float un = sqrtf(fmaxf(uu, EPS_));

        float ch = coshf(un);
        float sh = sinhf(un) / un;
        z0 = ch * z0 + sh * u0;
        z1 = ch * z1 + sh * u1;

        float znew0 = __shfl_sync(0xffffffffu, z0, 0);
        float v = acoshf(fmaxf(znew0, 1.0f + EPS_));
        bool spike = (v >= 1.0f);
        if (spike) { z0 = (lane == 0) ? 1.0f : 0.0f; z1 = 0.0f; }

        if (lane == 0) o_out[(size_t)t * NN + n] = spike ? 1.0f : 0.0f;
        float2 zz = make_float2(z0, z1);
        *reinterpret_cast<float2*>(z_out + (size_t)t * NN * OUT_DIM + base + c0) = zz;
    }
}

// ---------------- launch ----------------
extern "C" void kernel_launch(void* const* d_in, const int* in_sizes, int n_in,
                              void* d_out, int out_size) {
    const float* x  = (const float*)d_in[0];
    const int*   ei = (const int*)d_in[1];
    const float* W  = (const float*)d_in[2];
    const float* b  = (const float*)d_in[3];

    float* o_out = (float*)d_out;              // [T, N]
    float* z_out = o_out + (size_t)TT * NN;    // [T, N, 64]

    const int GEMM_SMEM = (IN_DIM * OUT_DIM / 2 + 64 * IN_DIM) * 8;  // 98304 B
    cudaFuncSetAttribute(gemm_kernel, cudaFuncAttributeMaxDynamicSharedMemorySize, GEMM_SMEM);

    init_kernel<<<(CSR_CAP + 255) / 256, 256>>>();
    hist_kernel<<<(EE + 255) / 256, 256>>>(ei + EE);
    scan_kernel<<<1, 1024>>>();
    gemm_kernel<<<(NN + 63) / 64, 256, GEMM_SMEM>>>(x, W);
    bucket_kernel<<<(EE + 255) / 256, 256>>>(ei);
    fused_kernel<<<(NN * 32 + 255) / 256, 256>>>(b, o_out, z_out);
}

// round 6
// speedup vs baseline: 2.2326x; 2.2326x over previous
#include <cuda_runtime.h>
#include <cstdint>

#define NN 100000
#define EE 1600000
#define IN_DIM 128
#define OUT_DIM 64
#define TT 8
#define EPS_ 1e-7f
#define CSR_CAP (EE + 8 * NN)

typedef unsigned long long ull;

// ---------------- scratch ----------------
__device__ int   g_cnt[NN];
__device__ int   g_off[NN];
__device__ int   g_cur[NN];
__device__ int   g_csr[CSR_CAP];                       // padding slots = NN (dummy)
__device__ float g_dinv[NN];
__device__ float g_hs[(size_t)(NN + 1) * OUT_DIM];     // dinv[n]*(x@W); row NN zeros
__device__ float g_h[(size_t)NN * OUT_DIM];            // aggregated + bias
__device__ int   g_cursor;

__device__ __forceinline__ void pfma(ull& acc, ull x, ull w) {
    asm("fma.rn.f32x2 %0, %1, %2, %0;" : "+l"(acc) : "l"(x), "l"(w));
}

// ---------------- kernels ----------------

__global__ void init_kernel() {
    int i = blockIdx.x * blockDim.x + threadIdx.x;
    if (i < CSR_CAP) g_csr[i] = NN;
    if (i < NN) g_cnt[i] = 0;
    if (i < OUT_DIM) g_hs[(size_t)NN * OUT_DIM + i] = 0.0f;
    if (i == 0) g_cursor = 0;
}

__global__ void hist_kernel(const int* __restrict__ dst) {
    int e = blockIdx.x * blockDim.x + threadIdx.x;
    if (e >= EE) return;
    atomicAdd(&g_cnt[dst[e]], 1);
}

// per-block scan + global bump allocator (bucket order is irrelevant)
__global__ void offsets_kernel() {
    int i = blockIdx.x * 1024 + threadIdx.x;
    int lane = threadIdx.x & 31, wid = threadIdx.x >> 5;
    int c = (i < NN) ? g_cnt[i] : 0;
    int pc = (c + 7) & ~7;

    int v = pc;
#pragma unroll
    for (int o = 1; o < 32; o <<= 1) {
        int t = __shfl_up_sync(0xffffffffu, v, o);
        if (lane >= o) v += t;
    }
    __shared__ int wsum[32];
    __shared__ int base;
    if (lane == 31) wsum[wid] = v;
    __syncthreads();
    if (wid == 0) {
        int w = wsum[lane];
#pragma unroll
        for (int o = 1; o < 32; o <<= 1) {
            int t = __shfl_up_sync(0xffffffffu, w, o);
            if (lane >= o) w += t;
        }
        wsum[lane] = w;
    }
    __syncthreads();
    int incl = v + ((wid > 0) ? wsum[wid - 1] : 0);
    if (threadIdx.x == 1023) base = atomicAdd(&g_cursor, incl);
    __syncthreads();
    if (i < NN) {
        int off = base + incl - pc;
        g_off[i] = off;
        g_cur[i] = off;
        g_dinv[i] = rsqrtf((float)(c + 1));
    }
}

// h_s = dinv * (x @ W): even-k in .lo, odd-k in .hi, no shuffles, no dup movs
__global__ void __launch_bounds__(256) gemm_kernel(const float* __restrict__ x,
                                                   const float* __restrict__ W) {
    extern __shared__ ull sm[];
    ull* Wp = sm;           // [64 kk][64 j]: (W[2kk][j], W[2kk+1][j])   32 KB
    ull* xs = sm + 4096;    // [64 node][64 kk]: (x[n][2kk], x[n][2kk+1]) 32 KB

    int tid = threadIdx.x;
    int n0 = blockIdx.x * 64;

    for (int i = tid; i < 64 * 64; i += 256) {
        int kk = i >> 6, j = i & 63;
        float w0 = W[(2 * kk) * OUT_DIM + j];
        float w1 = W[(2 * kk + 1) * OUT_DIM + j];
        ull p; asm("mov.b64 %0, {%1, %2};" : "=l"(p) : "f"(w0), "f"(w1));
        Wp[i] = p;
    }
    const ull* x2 = (const ull*)x;
    for (int i = tid; i < 64 * 64; i += 256) {
        int node = i >> 6, kk = i & 63;
        int gn = n0 + node;
        xs[i] = (gn < NN) ? x2[(size_t)gn * 64 + kk] : 0ull;
    }
    __syncthreads();

    int wid = tid >> 5, lane = tid & 31;
    const ull* xw = xs + wid * 8 * 64;

    ull a0[8], a1[8];
#pragma unroll
    for (int n = 0; n < 8; n++) { a0[n] = 0ull; a1[n] = 0ull; }

#pragma unroll 4
    for (int kk = 0; kk < 64; kk++) {
        ull w0 = Wp[kk * 64 + lane];
        ull w1 = Wp[kk * 64 + 32 + lane];
#pragma unroll
        for (int n = 0; n < 8; n++) {
            ull xv = xw[n * 64 + kk];
            pfma(a0[n], xv, w0);
            pfma(a1[n], xv, w1);
        }
    }

#pragma unroll
    for (int n = 0; n < 8; n++) {
        int gn = n0 + wid * 8 + n;
        if (gn >= NN) break;
        float lo, hi, lo1, hi1;
        asm("mov.b64 {%0, %1}, %2;" : "=f"(lo), "=f"(hi) : "l"(a0[n]));
        asm("mov.b64 {%0, %1}, %2;" : "=f"(lo1), "=f"(hi1) : "l"(a1[n]));
        float di = g_dinv[gn];
        g_hs[(size_t)gn * OUT_DIM + lane]      = (lo + hi) * di;
        g_hs[(size_t)gn * OUT_DIM + lane + 32] = (lo1 + hi1) * di;
    }
}

__global__ void bucket_kernel(const int* __restrict__ ei) {
    int e = blockIdx.x * blockDim.x + threadIdx.x;
    if (e >= EE) return;
    int s = ei[e];
    int d = ei[EE + e];
    int pos = atomicAdd(&g_cur[d], 1);
    g_csr[pos] = s;
}

// warp per node: gather in-edges, h = dinv[d]*sum + bias
__global__ void gather_kernel(const float* __restrict__ b) {
    int warp = (blockIdx.x * blockDim.x + threadIdx.x) >> 5;
    int lane = threadIdx.x & 31;
    if (warp >= NN) return;
    const int n = warp;

    int off = g_off[n];
    int mp = (g_cnt[n] + 7) & ~7;
    const float2* hs2 = (const float2*)g_hs;

    float2 acc = hs2[(size_t)n * 32 + lane];   // self loop (prescaled by dinv[n])

    for (int i = 0; i < mp; i += 8) {
        int4 a = __ldg((const int4*)(g_csr + off + i));
        int4 c = __ldg((const int4*)(g_csr + off + i + 4));
        float2 v0 = hs2[(size_t)a.x * 32 + lane];
        float2 v1 = hs2[(size_t)a.y * 32 + lane];
        float2 v2 = hs2[(size_t)a.z * 32 + lane];
        float2 v3 = hs2[(size_t)a.w * 32 + lane];
        float2 v4 = hs2[(size_t)c.x * 32 + lane];
        float2 v5 = hs2[(size_t)c.y * 32 + lane];
        float2 v6 = hs2[(size_t)c.z * 32 + lane];
        float2 v7 = hs2[(size_t)c.w * 32 + lane];
        acc.x += ((v0.x + v1.x) + (v2.x + v3.x)) + ((v4.x + v5.x) + (v6.x + v7.x));
        acc.y += ((v0.y + v1.y) + (v2.y + v3.y)) + ((v4.y + v5.y) + (v6.y + v7.y));
    }

    float di = g_dinv[n];
    float2 bb = ((const float2*)b)[lane];
    float2 out = make_float2(fmaf(di, acc.x, bb.x), fmaf(di, acc.y, bb.y));
    ((float2*)g_h)[(size_t)n * 32 + lane] = out;
}

// quad per node (4 lanes, 16 comps each): 8-step Lorentz recurrence
__global__ void __launch_bounds__(256) time_kernel(float* __restrict__ o_out,
                                                   float* __restrict__ z_out) {
    int gid = blockIdx.x * 256 + threadIdx.x;
    int node = gid >> 2;
    if (node >= NN) return;
    int q = gid & 3;

    const float4* hp = (const float4*)(g_h + (size_t)node * OUT_DIM + q * 16);
    float4 h[4], z[4], u[4];
#pragma unroll
    for (int j = 0; j < 4; j++) h[j] = hp[j];
#pragma unroll
    for (int j = 0; j < 4; j++) z[j] = make_float4(0.f, 0.f, 0.f, 0.f);
    if (q == 0) z[0].x = 1.0f;

#pragma unroll
    for (int t = 0; t < TT; t++) {
        float p = 0.f;
#pragma unroll
        for (int j = 0; j < 4; j++) {
            p = fmaf(z[j].x, h[j].x, p); p = fmaf(z[j].y, h[j].y, p);
            p = fmaf(z[j].z, h[j].z, p); p = fmaf(z[j].w, h[j].w, p);
        }
        p += __shfl_xor_sync(0xffffffffu, p, 1);
        p += __shfl_xor_sync(0xffffffffu, p, 2);
        float t00 = __shfl_sync(0xffffffffu, z[0].x * h[0].x, 0, 4);
        float lz = p - 2.0f * t00;

#pragma unroll
        for (int j = 0; j < 4; j++) {
            u[j].x = fmaf(lz, z[j].x, h[j].x);
            u[j].y = fmaf(lz, z[j].y, h[j].y);
            u[j].z = fmaf(lz, z[j].z, h[j].z);
            u[j].w = fmaf(lz, z[j].w, h[j].w);
        }
        float qq = 0.f;
#pragma unroll
        for (int j = 0; j < 4; j++) {
            qq = fmaf(u[j].x, u[j].x, qq); qq = fmaf(u[j].y, u[j].y, qq);
            qq = fmaf(u[j].z, u[j].z, qq); qq = fmaf(u[j].w, u[j].w, qq);
        }
        qq += __shfl_xor_sync(0xffffffffu, qq, 1);
        qq += __shfl_xor_sync(0xffffffffu, qq, 2);
        float u0 = __shfl_sync(0xffffffffu, u[0].x, 0, 4);
        float uu = qq - 2.0f * u0 * u0;

        float un = sqrtf(fmaxf(uu, EPS_));
        float ch = coshf(un);
        float sh = sinhf(un) / un;
#pragma unroll
        for (int j = 0; j < 4; j++) {
            z[j].x = fmaf(ch, z[j].x, sh * u[j].x);
            z[j].y = fmaf(ch, z[j].y, sh * u[j].y);
            z[j].z = fmaf(ch, z[j].z, sh * u[j].z);
            z[j].w = fmaf(ch, z[j].w, sh * u[j].w);
        }

        float z0b = __shfl_sync(0xffffffffu, z[0].x, 0, 4);
        float v = acoshf(fmaxf(z0b, 1.0f + EPS_));
        bool spike = (v >= 1.0f);
        if (spike) {
#pragma unroll
            for (int j = 0; j < 4; j++) z[j] = make_float4(0.f, 0.f, 0.f, 0.f);
            if (q == 0) z[0].x = 1.0f;
        }

        if (q == 0) o_out[(size_t)t * NN + node] = spike ? 1.0f : 0.0f;
        float4* zp = (float4*)(z_out + (size_t)t * NN * OUT_DIM + (size_t)node * OUT_DIM + q * 16);
#pragma unroll
        for (int j = 0; j < 4; j++) zp[j] = z[j];
    }
}

// ---------------- launch ----------------
extern "C" void kernel_launch(void* const* d_in, const int* in_sizes, int n_in,
                              void* d_out, int out_size) {
    const float* x  = (const float*)d_in[0];
    const int*   ei = (const int*)d_in[1];
    const float* W  = (const float*)d_in[2];
    const float* b  = (const float*)d_in[3];

    float* o_out = (float*)d_out;              // [T, N]
    float* z_out = o_out + (size_t)TT * NN;    // [T, N, 64]

    const int GEMM_SMEM = 65536;
    cudaFuncSetAttribute(gemm_kernel, cudaFuncAttributeMaxDynamicSharedMemorySize, GEMM_SMEM);

    init_kernel<<<(CSR_CAP + 255) / 256, 256>>>();
    hist_kernel<<<(EE + 255) / 256, 256>>>(ei + EE);
    offsets_kernel<<<(NN + 1023) / 1024, 1024>>>();
    gemm_kernel<<<(NN + 63) / 64, 256, GEMM_SMEM>>>(x, W);
    bucket_kernel<<<(EE + 255) / 256, 256>>>(ei);
    gather_kernel<<<(NN * 32 + 255) / 256, 256>>>(b);
    time_kernel<<<(NN * 4 + 255) / 256, 256>>>(o_out, z_out);
}

// round 7
// speedup vs baseline: 2.2503x; 1.0079x over previous
#include <cuda_runtime.h>
#include <cstdint>

#define NN 100000
#define EE 1600000
#define IN_DIM 128
#define OUT_DIM 64
#define TT 8
#define EPS_ 1e-7f
#define CSR_CAP (EE + 8 * NN)
#define NB 48                     // nodes per GEMM block

typedef unsigned long long ull;

// ---------------- scratch ----------------
__device__ int   g_cnt[NN];
__device__ int   g_off[NN];
__device__ int   g_cur[NN];
__device__ int   g_csr[CSR_CAP];                       // padding slots = NN (dummy)
__device__ float g_dinv[NN];
__device__ float g_hs[(size_t)(NN + 1) * OUT_DIM];     // dinv[n]*(x@W); row NN zeros
__device__ float g_h[(size_t)NN * OUT_DIM];            // aggregated + bias
__device__ int   g_cursor;

__device__ __forceinline__ void pfma(ull& acc, ull x, ull w) {
    asm("fma.rn.f32x2 %0, %1, %2, %0;" : "+l"(acc) : "l"(x), "l"(w));
}

// ---------------- kernels ----------------

__global__ void init_kernel() {
    int i = blockIdx.x * blockDim.x + threadIdx.x;
    if (i < NN) g_cnt[i] = 0;
    if (i < OUT_DIM) g_hs[(size_t)NN * OUT_DIM + i] = 0.0f;
    if (i == 0) g_cursor = 0;
}

__global__ void hist_kernel(const int* __restrict__ dst) {
    int e = blockIdx.x * blockDim.x + threadIdx.x;
    if (e >= EE) return;
    atomicAdd(&g_cnt[dst[e]], 1);
}

// per-block scan + global bump allocator; also writes CSR padding slots
__global__ void offsets_kernel() {
    int i = blockIdx.x * 1024 + threadIdx.x;
    int lane = threadIdx.x & 31, wid = threadIdx.x >> 5;
    int c = (i < NN) ? g_cnt[i] : 0;
    int pc = (c + 7) & ~7;

    int v = pc;
#pragma unroll
    for (int o = 1; o < 32; o <<= 1) {
        int t = __shfl_up_sync(0xffffffffu, v, o);
        if (lane >= o) v += t;
    }
    __shared__ int wsum[32];
    __shared__ int base;
    if (lane == 31) wsum[wid] = v;
    __syncthreads();
    if (wid == 0) {
        int w = wsum[lane];
#pragma unroll
        for (int o = 1; o < 32; o <<= 1) {
            int t = __shfl_up_sync(0xffffffffu, w, o);
            if (lane >= o) w += t;
        }
        wsum[lane] = w;
    }
    __syncthreads();
    int incl = v + ((wid > 0) ? wsum[wid - 1] : 0);
    if (threadIdx.x == 1023) base = atomicAdd(&g_cursor, incl);
    __syncthreads();
    if (i < NN) {
        int off = base + incl - pc;
        g_off[i] = off;
        g_cur[i] = off;
        g_dinv[i] = rsqrtf((float)(c + 1));
        for (int j = c; j < pc; j++) g_csr[off + j] = NN;   // dummy padding
    }
}

// h_s = dinv * (x @ W): 48 nodes/block (56KB smem -> 4 CTAs/SM), LDS.128 reads,
// even-k in .lo / odd-k in .hi of packed f32x2 accumulators
__global__ void __launch_bounds__(256) gemm_kernel(const float* __restrict__ x,
                                                   const float* __restrict__ W) {
    extern __shared__ ull sm[];
    ull* Wq = sm;            // [32 kk2][64 j][2] : {(W[4kk2][j],W[4kk2+1][j]), (W[4kk2+2][j],W[4kk2+3][j])}  32 KB
    ull* xs = sm + 4096;     // [48 node][64 kk]  : (x[n][2kk], x[n][2kk+1])   24 KB

    int tid = threadIdx.x;
    int n0 = blockIdx.x * NB;

    for (int i = tid; i < 64 * 64; i += 256) {
        int kk = i >> 6, j = i & 63;
        int kk2 = kk >> 1, lo = kk & 1;
        float w0 = W[(2 * kk) * OUT_DIM + j];
        float w1 = W[(2 * kk + 1) * OUT_DIM + j];
        ull p; asm("mov.b64 %0, {%1, %2};" : "=l"(p) : "f"(w0), "f"(w1));
        Wq[kk2 * 128 + j * 2 + lo] = p;
    }
    const ull* x2 = (const ull*)x;
    for (int i = tid; i < NB * 64; i += 256) {
        int node = i >> 6, kk = i & 63;
        int gn = n0 + node;
        xs[i] = (gn < NN) ? x2[(size_t)gn * 64 + kk] : 0ull;
    }
    __syncthreads();

    int wid = tid >> 5, lane = tid & 31;
    const ull* xw = xs + wid * 6 * 64;     // 6 nodes per warp

    ull a0[6], a1[6];
#pragma unroll
    for (int n = 0; n < 6; n++) { a0[n] = 0ull; a1[n] = 0ull; }

#pragma unroll 4
    for (int kk2 = 0; kk2 < 32; kk2++) {
        ulonglong2 wa = *(const ulonglong2*)(Wq + kk2 * 128 + 2 * lane);
        ulonglong2 wb = *(const ulonglong2*)(Wq + kk2 * 128 + 2 * (lane + 32));
#pragma unroll
        for (int n = 0; n < 6; n++) {
            ulonglong2 xv = *(const ulonglong2*)(xw + n * 64 + 2 * kk2);
            pfma(a0[n], xv.x, wa.x);
            pfma(a1[n], xv.x, wb.x);
            pfma(a0[n], xv.y, wa.y);
            pfma(a1[n], xv.y, wb.y);
        }
    }

#pragma unroll
    for (int n = 0; n < 6; n++) {
        int gn = n0 + wid * 6 + n;
        if (gn >= NN) break;
        float lo, hi, lo1, hi1;
        asm("mov.b64 {%0, %1}, %2;" : "=f"(lo), "=f"(hi) : "l"(a0[n]));
        asm("mov.b64 {%0, %1}, %2;" : "=f"(lo1), "=f"(hi1) : "l"(a1[n]));
        float di = g_dinv[gn];
        g_hs[(size_t)gn * OUT_DIM + lane]      = (lo + hi) * di;
        g_hs[(size_t)gn * OUT_DIM + lane + 32] = (lo1 + hi1) * di;
    }
}

__global__ void bucket_kernel(const int* __restrict__ ei) {
    int e = blockIdx.x * blockDim.x + threadIdx.x;
    if (e >= EE) return;
    int s = ei[e];
    int d = ei[EE + e];
    int pos = atomicAdd(&g_cur[d], 1);
    g_csr[pos] = s;
}

// warp per node: gather in-edges, h = dinv[d]*sum + bias
__global__ void gather_kernel(const float* __restrict__ b) {
    int warp = (blockIdx.x * blockDim.x + threadIdx.x) >> 5;
    int lane = threadIdx.x & 31;
    if (warp >= NN) return;
    const int n = warp;

    int off = g_off[n];
    int mp = (g_cnt[n] + 7) & ~7;
    const float2* hs2 = (const float2*)g_hs;

    float2 acc = hs2[(size_t)n * 32 + lane];   // self loop (prescaled by dinv[n])

    for (int i = 0; i < mp; i += 8) {
        int4 a = __ldg((const int4*)(g_csr + off + i));
        int4 c = __ldg((const int4*)(g_csr + off + i + 4));
        float2 v0 = hs2[(size_t)a.x * 32 + lane];
        float2 v1 = hs2[(size_t)a.y * 32 + lane];
        float2 v2 = hs2[(size_t)a.z * 32 + lane];
        float2 v3 = hs2[(size_t)a.w * 32 + lane];
        float2 v4 = hs2[(size_t)c.x * 32 + lane];
        float2 v5 = hs2[(size_t)c.y * 32 + lane];
        float2 v6 = hs2[(size_t)c.z * 32 + lane];
        float2 v7 = hs2[(size_t)c.w * 32 + lane];
        acc.x += ((v0.x + v1.x) + (v2.x + v3.x)) + ((v4.x + v5.x) + (v6.x + v7.x));
        acc.y += ((v0.y + v1.y) + (v2.y + v3.y)) + ((v4.y + v5.y) + (v6.y + v7.y));
    }

    float di = g_dinv[n];
    float2 bb = ((const float2*)b)[lane];
    float2 out = make_float2(fmaf(di, acc.x, bb.x), fmaf(di, acc.y, bb.y));
    ((float2*)g_h)[(size_t)n * 32 + lane] = out;
}

// quad per node (4 lanes, 16 comps each): 8-step Lorentz recurrence
__global__ void __launch_bounds__(256) time_kernel(float* __restrict__ o_out,
                                                   float* __restrict__ z_out) {
    int gid = blockIdx.x * 256 + threadIdx.x;
    int node = gid >> 2;
    if (node >= NN) return;
    int q = gid & 3;

    const float4* hp = (const float4*)(g_h + (size_t)node * OUT_DIM + q * 16);
    float4 h[4], z[4], u[4];
#pragma unroll
    for (int j = 0; j < 4; j++) h[j] = hp[j];
#pragma unroll
    for (int j = 0; j < 4; j++) z[j] = make_float4(0.f, 0.f, 0.f, 0.f);
    if (q == 0) z[0].x = 1.0f;

#pragma unroll
    for (int t = 0; t < TT; t++) {
        float p = 0.f;
#pragma unroll
        for (int j = 0; j < 4; j++) {
            p = fmaf(z[j].x, h[j].x, p); p = fmaf(z[j].y, h[j].y, p);
            p = fmaf(z[j].z, h[j].z, p); p = fmaf(z[j].w, h[j].w, p);
        }
        p += __shfl_xor_sync(0xffffffffu, p, 1);
        p += __shfl_xor_sync(0xffffffffu, p, 2);
        float t00 = __shfl_sync(0xffffffffu, z[0].x * h[0].x, 0, 4);
        float lz = p - 2.0f * t00;

#pragma unroll
        for (int j = 0; j < 4; j++) {
            u[j].x = fmaf(lz, z[j].x, h[j].x);
            u[j].y = fmaf(lz, z[j].y, h[j].y);
            u[j].z = fmaf(lz, z[j].z, h[j].z);
            u[j].w = fmaf(lz, z[j].w, h[j].w);
        }
        float qq = 0.f;
#pragma unroll
        for (int j = 0; j < 4; j++) {
            qq = fmaf(u[j].x, u[j].x, qq); qq = fmaf(u[j].y, u[j].y, qq);
            qq = fmaf(u[j].z, u[j].z, qq); qq = fmaf(u[j].w, u[j].w, qq);
        }
        qq += __shfl_xor_sync(0xffffffffu, qq, 1);
        qq += __shfl_xor_sync(0xffffffffu, qq, 2);
        float u0 = __shfl_sync(0xffffffffu, u[0].x, 0, 4);
        float uu = qq - 2.0f * u0 * u0;

        float un = sqrtf(fmaxf(uu, EPS_));
        float ch = coshf(un);
        float sh = sinhf(un) / un;
#pragma unroll
        for (int j = 0; j < 4; j++) {
            z[j].x = fmaf(ch, z[j].x, sh * u[j].x);
            z[j].y = fmaf(ch, z[j].y, sh * u[j].y);
            z[j].z = fmaf(ch, z[j].z, sh * u[j].z);
            z[j].w = fmaf(ch, z[j].w, sh * u[j].w);
        }

        float z0b = __shfl_sync(0xffffffffu, z[0].x, 0, 4);
        float v = acoshf(fmaxf(z0b, 1.0f + EPS_));
        bool spike = (v >= 1.0f);
        if (spike) {
#pragma unroll
            for (int j = 0; j < 4; j++) z[j] = make_float4(0.f, 0.f, 0.f, 0.f);
            if (q == 0) z[0].x = 1.0f;
        }

        if (q == 0) o_out[(size_t)t * NN + node] = spike ? 1.0f : 0.0f;
        float4* zp = (float4*)(z_out + (size_t)t * NN * OUT_DIM + (size_t)node * OUT_DIM + q * 16);
#pragma unroll
        for (int j = 0; j < 4; j++) zp[j] = z[j];
    }
}

// ---------------- launch ----------------
extern "C" void kernel_launch(void* const* d_in, const int* in_sizes, int n_in,
                              void* d_out, int out_size) {
    const float* x  = (const float*)d_in[0];
    const int*   ei = (const int*)d_in[1];
    const float* W  = (const float*)d_in[2];
    const float* b  = (const float*)d_in[3];

    float* o_out = (float*)d_out;              // [T, N]
    float* z_out = o_out + (size_t)TT * NN;    // [T, N, 64]

    const int GEMM_SMEM = (4096 + NB * 64) * 8;   // 57344 B -> 4 CTAs/SM
    cudaFuncSetAttribute(gemm_kernel, cudaFuncAttributeMaxDynamicSharedMemorySize, GEMM_SMEM);

    init_kernel<<<(NN + 255) / 256, 256>>>();
    hist_kernel<<<(EE + 255) / 256, 256>>>(ei + EE);
    offsets_kernel<<<(NN + 1023) / 1024, 1024>>>();
    gemm_kernel<<<(NN + NB - 1) / NB, 256, GEMM_SMEM>>>(x, W);
    bucket_kernel<<<(EE + 255) / 256, 256>>>(ei);
    gather_kernel<<<(NN * 32 + 255) / 256, 256>>>(b);
    time_kernel<<<(NN * 4 + 255) / 256, 256>>>(o_out, z_out);
}

// round 8
// speedup vs baseline: 2.5420x; 1.1296x over previous
#include <cuda_runtime.h>
#include <cstdint>

#define NN 100000
#define EE 1600000
#define IN_DIM 128
#define OUT_DIM 64
#define TT 8
#define EPS_ 1e-7f
#define CSR_CAP (EE + 8 * NN)
#define NB 48                     // nodes per GEMM block (4 warps x 12)

typedef unsigned long long ull;

// ---------------- scratch ----------------
__device__ int   g_cnt[NN];
__device__ int   g_off[NN];
__device__ int   g_cur[NN];
__device__ int   g_csr[CSR_CAP];                       // padding slots = NN (dummy)
__device__ float g_dinv[NN];
__device__ float g_hs[(size_t)(NN + 1) * OUT_DIM];     // dinv[n]*(x@W); row NN zeros
__device__ float g_h[(size_t)NN * OUT_DIM];            // aggregated + bias
__device__ int   g_cursor;

__device__ __forceinline__ void pfma(ull& acc, ull x, ull w) {
    asm("fma.rn.f32x2 %0, %1, %2, %0;" : "+l"(acc) : "l"(x), "l"(w));
}

// ---------------- kernels ----------------

__global__ void init_kernel() {
    int i = blockIdx.x * blockDim.x + threadIdx.x;
    if (i < NN) g_cnt[i] = 0;
    if (i < OUT_DIM) g_hs[(size_t)NN * OUT_DIM + i] = 0.0f;
    if (i == 0) g_cursor = 0;
}

__global__ void hist_kernel(const int* __restrict__ dst) {
    int e = blockIdx.x * blockDim.x + threadIdx.x;
    if (e >= EE) return;
    atomicAdd(&g_cnt[dst[e]], 1);
}

// per-block scan + global bump allocator; also writes CSR padding slots
__global__ void offsets_kernel() {
    int i = blockIdx.x * 1024 + threadIdx.x;
    int lane = threadIdx.x & 31, wid = threadIdx.x >> 5;
    int c = (i < NN) ? g_cnt[i] : 0;
    int pc = (c + 7) & ~7;

    int v = pc;
#pragma unroll
    for (int o = 1; o < 32; o <<= 1) {
        int t = __shfl_up_sync(0xffffffffu, v, o);
        if (lane >= o) v += t;
    }
    __shared__ int wsum[32];
    __shared__ int base;
    if (lane == 31) wsum[wid] = v;
    __syncthreads();
    if (wid == 0) {
        int w = wsum[lane];
#pragma unroll
        for (int o = 1; o < 32; o <<= 1) {
            int t = __shfl_up_sync(0xffffffffu, w, o);
            if (lane >= o) w += t;
        }
        wsum[lane] = w;
    }
    __syncthreads();
    int incl = v + ((wid > 0) ? wsum[wid - 1] : 0);
    if (threadIdx.x == 1023) base = atomicAdd(&g_cursor, incl);
    __syncthreads();
    if (i < NN) {
        int off = base + incl - pc;
        g_off[i] = off;
        g_cur[i] = off;
        g_dinv[i] = rsqrtf((float)(c + 1));
        for (int j = c; j < pc; j++) g_csr[off + j] = NN;   // dummy padding
    }
}

// h_s = dinv * (x @ W): 12 nodes per warp, 4 warps/block (NB=48).
// even-k in .lo / odd-k in .hi of packed f32x2 accumulators; LDS.128 reads.
__global__ void __launch_bounds__(128) gemm_kernel(const float* __restrict__ x,
                                                   const float* __restrict__ W) {
    extern __shared__ ull sm[];
    ull* Wq = sm;            // [32 kk2][64 j][2] pairs-of-pairs, 32 KB
    ull* xs = sm + 4096;     // [48 node][64 kk] : (x[n][2kk], x[n][2kk+1]), 24 KB

    int tid = threadIdx.x;
    int n0 = blockIdx.x * NB;

    for (int i = tid; i < 64 * 64; i += 128) {
        int kk = i >> 6, j = i & 63;
        int kk2 = kk >> 1, lo = kk & 1;
        float w0 = W[(2 * kk) * OUT_DIM + j];
        float w1 = W[(2 * kk + 1) * OUT_DIM + j];
        ull p; asm("mov.b64 %0, {%1, %2};" : "=l"(p) : "f"(w0), "f"(w1));
        Wq[kk2 * 128 + j * 2 + lo] = p;
    }
    const ull* x2 = (const ull*)x;
    for (int i = tid; i < NB * 64; i += 128) {
        int node = i >> 6, kk = i & 63;
        int gn = n0 + node;
        xs[i] = (gn < NN) ? x2[(size_t)gn * 64 + kk] : 0ull;
    }
    __syncthreads();

    int wid = tid >> 5, lane = tid & 31;
    const ull* xw = xs + wid * 12 * 64;     // 12 nodes per warp

    ull a0[12], a1[12];
#pragma unroll
    for (int n = 0; n < 12; n++) { a0[n] = 0ull; a1[n] = 0ull; }

#pragma unroll 2
    for (int kk2 = 0; kk2 < 32; kk2++) {
        ulonglong2 wa = *(const ulonglong2*)(Wq + kk2 * 128 + 2 * lane);
        ulonglong2 wb = *(const ulonglong2*)(Wq + kk2 * 128 + 2 * (lane + 32));
#pragma unroll
        for (int n = 0; n < 12; n++) {
            ulonglong2 xv = *(const ulonglong2*)(xw + n * 64 + 2 * kk2);   // broadcast
            pfma(a0[n], xv.x, wa.x);
            pfma(a1[n], xv.x, wb.x);
            pfma(a0[n], xv.y, wa.y);
            pfma(a1[n], xv.y, wb.y);
        }
    }

#pragma unroll
    for (int n = 0; n < 12; n++) {
        int gn = n0 + wid * 12 + n;
        if (gn >= NN) break;
        float lo, hi, lo1, hi1;
        asm("mov.b64 {%0, %1}, %2;" : "=f"(lo), "=f"(hi) : "l"(a0[n]));
        asm("mov.b64 {%0, %1}, %2;" : "=f"(lo1), "=f"(hi1) : "l"(a1[n]));
        float di = g_dinv[gn];
        g_hs[(size_t)gn * OUT_DIM + lane]      = (lo + hi) * di;
        g_hs[(size_t)gn * OUT_DIM + lane + 32] = (lo1 + hi1) * di;
    }
}

__global__ void bucket_kernel(const int* __restrict__ ei) {
    int e = blockIdx.x * blockDim.x + threadIdx.x;
    if (e >= EE) return;
    int s = ei[e];
    int d = ei[EE + e];
    int pos = atomicAdd(&g_cur[d], 1);
    g_csr[pos] = s;
}

// warp per node: gather in-edges, h = dinv[d]*sum + bias
__global__ void gather_kernel(const float* __restrict__ b) {
    int warp = (blockIdx.x * blockDim.x + threadIdx.x) >> 5;
    int lane = threadIdx.x & 31;
    if (warp >= NN) return;
    const int n = warp;

    int off = g_off[n];
    int mp = (g_cnt[n] + 7) & ~7;
    const float2* hs2 = (const float2*)g_hs;

    float2 acc = hs2[(size_t)n * 32 + lane];   // self loop (prescaled by dinv[n])

    for (int i = 0; i < mp; i += 8) {
        int4 a = __ldg((const int4*)(g_csr + off + i));
        int4 c = __ldg((const int4*)(g_csr + off + i + 4));
        float2 v0 = hs2[(size_t)a.x * 32 + lane];
        float2 v1 = hs2[(size_t)a.y * 32 + lane];
        float2 v2 = hs2[(size_t)a.z * 32 + lane];
        float2 v3 = hs2[(size_t)a.w * 32 + lane];
        float2 v4 = hs2[(size_t)c.x * 32 + lane];
        float2 v5 = hs2[(size_t)c.y * 32 + lane];
        float2 v6 = hs2[(size_t)c.z * 32 + lane];
        float2 v7 = hs2[(size_t)c.w * 32 + lane];
        acc.x += ((v0.x + v1.x) + (v2.x + v3.x)) + ((v4.x + v5.x) + (v6.x + v7.x));
        acc.y += ((v0.y + v1.y) + (v2.y + v3.y)) + ((v4.y + v5.y) + (v6.y + v7.y));
    }

    float di = g_dinv[n];
    float2 bb = ((const float2*)b)[lane];
    float2 out = make_float2(fmaf(di, acc.x, bb.x), fmaf(di, acc.y, bb.y));
    ((float2*)g_h)[(size_t)n * 32 + lane] = out;
}

// quad per node (4 lanes, 16 comps each): 8-step Lorentz recurrence
__global__ void __launch_bounds__(256) time_kernel(float* __restrict__ o_out,
                                                   float* __restrict__ z_out) {
    int gid = blockIdx.x * 256 + threadIdx.x;
    int node = gid >> 2;
    if (node >= NN) return;
    int q = gid & 3;

    const float4* hp = (const float4*)(g_h + (size_t)node * OUT_DIM + q * 16);
    float4 h[4], z[4], u[4];
#pragma unroll
    for (int j = 0; j < 4; j++) h[j] = hp[j];
#pragma unroll
    for (int j = 0; j < 4; j++) z[j] = make_float4(0.f, 0.f, 0.f, 0.f);
    if (q == 0) z[0].x = 1.0f;

#pragma unroll
    for (int t = 0; t < TT; t++) {
        float p = 0.f;
#pragma unroll
        for (int j = 0; j < 4; j++) {
            p = fmaf(z[j].x, h[j].x, p); p = fmaf(z[j].y, h[j].y, p);
            p = fmaf(z[j].z, h[j].z, p); p = fmaf(z[j].w, h[j].w, p);
        }
        p += __shfl_xor_sync(0xffffffffu, p, 1);
        p += __shfl_xor_sync(0xffffffffu, p, 2);
        float t00 = __shfl_sync(0xffffffffu, z[0].x * h[0].x, 0, 4);
        float lz = p - 2.0f * t00;

#pragma unroll
        for (int j = 0; j < 4; j++) {
            u[j].x = fmaf(lz, z[j].x, h[j].x);
            u[j].y = fmaf(lz, z[j].y, h[j].y);
            u[j].z = fmaf(lz, z[j].z, h[j].z);
            u[j].w = fmaf(lz, z[j].w, h[j].w);
        }
        float qq = 0.f;
#pragma unroll
        for (int j = 0; j < 4; j++) {
            qq = fmaf(u[j].x, u[j].x, qq); qq = fmaf(u[j].y, u[j].y, qq);
            qq = fmaf(u[j].z, u[j].z, qq); qq = fmaf(u[j].w, u[j].w, qq);
        }
        qq += __shfl_xor_sync(0xffffffffu, qq, 1);
        qq += __shfl_xor_sync(0xffffffffu, qq, 2);
        float u0 = __shfl_sync(0xffffffffu, u[0].x, 0, 4);
        float uu = qq - 2.0f * u0 * u0;

        float un = sqrtf(fmaxf(uu, EPS_));
        float ch = coshf(un);
        float sh = sinhf(un) / un;
#pragma unroll
        for (int j = 0; j < 4; j++) {
            z[j].x = fmaf(ch, z[j].x, sh * u[j].x);
            z[j].y = fmaf(ch, z[j].y, sh * u[j].y);
            z[j].z = fmaf(ch, z[j].z, sh * u[j].z);
            z[j].w = fmaf(ch, z[j].w, sh * u[j].w);
        }

        float z0b = __shfl_sync(0xffffffffu, z[0].x, 0, 4);
        float v = acoshf(fmaxf(z0b, 1.0f + EPS_));
        bool spike = (v >= 1.0f);
        if (spike) {
#pragma unroll
            for (int j = 0; j < 4; j++) z[j] = make_float4(0.f, 0.f, 0.f, 0.f);
            if (q == 0) z[0].x = 1.0f;
        }

        if (q == 0) o_out[(size_t)t * NN + node] = spike ? 1.0f : 0.0f;
        float4* zp = (float4*)(z_out + (size_t)t * NN * OUT_DIM + (size_t)node * OUT_DIM + q * 16);
#pragma unroll
        for (int j = 0; j < 4; j++) zp[j] = z[j];
    }
}

// ---------------- launch ----------------
extern "C" void kernel_launch(void* const* d_in, const int* in_sizes, int n_in,
                              void* d_out, int out_size) {
    const float* x  = (const float*)d_in[0];
    const int*   ei = (const int*)d_in[1];
    const float* W  = (const float*)d_in[2];
    const float* b  = (const float*)d_in[3];

    float* o_out = (float*)d_out;              // [T, N]
    float* z_out = o_out + (size_t)TT * NN;    // [T, N, 64]

    const int GEMM_SMEM = (4096 + NB * 64) * 8;   // 57344 B -> 4 CTAs/SM
    cudaFuncSetAttribute(gemm_kernel, cudaFuncAttributeMaxDynamicSharedMemorySize, GEMM_SMEM);

    init_kernel<<<(NN + 255) / 256, 256>>>();
    hist_kernel<<<(EE + 255) / 256, 256>>>(ei + EE);
    offsets_kernel<<<(NN + 1023) / 1024, 1024>>>();
    gemm_kernel<<<(NN + NB - 1) / NB, 128, GEMM_SMEM>>>(x, W);
    bucket_kernel<<<(EE + 255) / 256, 256>>>(ei);
    gather_kernel<<<(NN * 32 + 255) / 256, 256>>>(b);
    time_kernel<<<(NN * 4 + 255) / 256, 256>>>(o_out, z_out);
}